// round 5
// baseline (speedup 1.0000x reference)
#include <cuda_runtime.h>
#include <cstdint>

#define B_   256
#define T_   2048
#define IN_  128
#define H_   64
#define G_   256   // 4*H

// Scratch (allocation-free rule: static __device__ array)
__device__ float g_xp[(size_t)B_ * T_ * G_];   // precomputed x@W_ih1^T + b_ih1 + b_hh1

typedef unsigned long long u64;

// ---------------- helpers ----------------
__device__ __forceinline__ void ffma2(u64& d, u64 a, u64 b) {
    asm("fma.rn.f32x2 %0, %1, %2, %0;" : "+l"(d) : "l"(a), "l"(b));
}
__device__ __forceinline__ float2 unpk(u64 p) {
    float2 r;
    asm("mov.b64 {%0, %1}, %2;" : "=f"(r.x), "=f"(r.y) : "l"(p));
    return r;
}
__device__ __forceinline__ u64 dup2(float a) {
    u64 r;
    asm("mov.b64 %0, {%1, %1};" : "=l"(r) : "f"(a));
    return r;
}
__device__ __forceinline__ float sigf(float x) {
    return __fdividef(1.0f, 1.0f + __expf(-x));
}
__device__ __forceinline__ float tanhf_(float x) {
    float a = fabsf(x);
    float e = __expf(2.0f * a);                 // inf-safe
    float r = 1.0f - __fdividef(2.0f, e + 1.0f);
    return copysignf(r, x);
}
__device__ __forceinline__ void cp_async16(void* dst_smem, const void* src_gmem) {
    unsigned saddr = (unsigned)__cvta_generic_to_shared(dst_smem);
    asm volatile("cp.async.cg.shared.global [%0], [%1], 16;" ::
                 "r"(saddr), "l"(src_gmem));
}
__device__ __forceinline__ void cp_commit() {
    asm volatile("cp.async.commit_group;");
}
__device__ __forceinline__ void cp_wait0() {
    asm volatile("cp.async.wait_group 0;");
}

// ---------------- kernel 1: xp = x @ W_ih1^T + b_ih1 + b_hh1 ----------------
// Reads W directly (row-major, k contiguous); k-paired f32x2 accumulators.
// M = B*T = 524288, N = 256, K = 128. BM=64, BN=64, 256 threads, 4x4 tile.
__global__ __launch_bounds__(256) void xp_gemm(const float* __restrict__ x,
                                               const float* __restrict__ W,
                                               const float* __restrict__ bih,
                                               const float* __restrict__ bhh) {
    __shared__ float Xs[64][128];              // 32 KB
    int tid = threadIdx.x;
    size_t mbase = (size_t)blockIdx.x * 64;
    int nbase = blockIdx.y * 64;

    const float* xg = x + mbase * IN_;
#pragma unroll
    for (int i = 0; i < 8; i++) {
        int idx = tid + i * 256;
        int m = idx >> 5, k4 = (idx & 31) << 2;
        *(float4*)&Xs[m][k4] = *(const float4*)(xg + m * IN_ + k4);
    }
    __syncthreads();

    int tx = tid & 15, ty = tid >> 4;
    int n0 = nbase + tx * 4;
    int m0 = ty * 4;

    u64 acc[4][4];   // [m][n], k-paired
#pragma unroll
    for (int i = 0; i < 4; i++)
#pragma unroll
        for (int j = 0; j < 4; j++) acc[i][j] = 0ull;

#pragma unroll 4
    for (int k4 = 0; k4 < IN_; k4 += 4) {      // 32 iters, 4 k per iter
        u64 wv[4][2];                          // W[n0+j][k4..k4+4) as 2 k-pairs
#pragma unroll
        for (int j = 0; j < 4; j++) {
            ulonglong2 t2 = *(const ulonglong2*)(W + (size_t)(n0 + j) * IN_ + k4);
            wv[j][0] = t2.x; wv[j][1] = t2.y;
        }
#pragma unroll
        for (int i = 0; i < 4; i++) {
            ulonglong2 xv = *(const ulonglong2*)&Xs[m0 + i][k4];
#pragma unroll
            for (int j = 0; j < 4; j++) {
                ffma2(acc[i][j], xv.x, wv[j][0]);
                ffma2(acc[i][j], xv.y, wv[j][1]);
            }
        }
    }

    float4 bs;
    bs.x = bih[n0 + 0] + bhh[n0 + 0];
    bs.y = bih[n0 + 1] + bhh[n0 + 1];
    bs.z = bih[n0 + 2] + bhh[n0 + 2];
    bs.w = bih[n0 + 3] + bhh[n0 + 3];
#pragma unroll
    for (int i = 0; i < 4; i++) {
        float4 o;
        float2 p;
        p = unpk(acc[i][0]); o.x = p.x + p.y + bs.x;
        p = unpk(acc[i][1]); o.y = p.x + p.y + bs.y;
        p = unpk(acc[i][2]); o.z = p.x + p.y + bs.z;
        p = unpk(acc[i][3]); o.w = p.x + p.y + bs.w;
        *(float4*)(g_xp + (mbase + m0 + i) * G_ + n0) = o;
    }
}

// ---------------- kernel 2: fused 2-layer LSTM recurrence + output head ----------------
// 128 CTAs x 256 threads, 2 batch rows per CTA (both rows per thread).
// Thread tid: q = tid>>2 (gate quad, gates 4q..4q+3), s = tid&3 (K split).
//   Layer-1 dot: k in [16s, 16s+16)  over h1 (64).
//   Layer-2 dot: kcat in [32s, 32s+32) over concat [h1new(64); h2prev(64)].
// Weights in registers: 4*16 + 4*32 = 192 floats = 96 x f32x2 regs.
// xp streamed in via cp.async double-buffered smem (no registers held).
__global__ __launch_bounds__(256, 1) void lstm_rec(
    const float* __restrict__ Whh1, const float* __restrict__ Wih2,
    const float* __restrict__ Whh2, const float* __restrict__ bih2,
    const float* __restrict__ bhh2, const float* __restrict__ Wout,
    const float* __restrict__ bout, float* __restrict__ out) {
    __shared__ float h1s[2][64];
    __shared__ float h2s[2][64];
    __shared__ float ga[2][256];      // [row][gate]
    __shared__ float gb[2][256];
    __shared__ __align__(16) float xbuf[2][2][256];  // [parity][row][gate]
    __shared__ float red[4];

    int tid = threadIdx.x;
    int q = tid >> 2, s = tid & 3;
    int g0 = q * 4;

    // ---- load weights into registers ----
    u64 w1[4][8];    // [gate][k-pair]  k in [16s,16s+16)
    u64 w2[4][16];   // [gate][kc-pair] kcat in [32s,32s+32)
#pragma unroll
    for (int g = 0; g < 4; g++) {
        const u64* p1 = (const u64*)(Whh1 + (g0 + g) * 64 + s * 16);
#pragma unroll
        for (int j = 0; j < 8; j++) w1[g][j] = p1[j];
        const float* b2 = (s < 2) ? (Wih2 + (g0 + g) * 64 + s * 32)
                                  : (Whh2 + (g0 + g) * 64 + (s - 2) * 32);
        const u64* p2 = (const u64*)b2;
#pragma unroll
        for (int j = 0; j < 16; j++) w2[g][j] = p2[j];
    }
    float4 bias2v;
    bias2v.x = bih2[g0 + 0] + bhh2[g0 + 0];
    bias2v.y = bih2[g0 + 1] + bhh2[g0 + 1];
    bias2v.z = bih2[g0 + 2] + bhh2[g0 + 2];
    bias2v.w = bih2[g0 + 3] + bhh2[g0 + 3];

    // update-thread state (tid < 128): row ur, unit uu
    int ur = tid >> 6, uu = tid & 63;
    float wo = (tid < 128) ? Wout[uu] : 0.0f;
    float bo = bout[0];
    float c1v = 0.0f, c2v = 0.0f;

    int b0 = blockIdx.x * 2;
    // copy thread (tid<128): copies xp 16B chunk (row pr, gates pc..pc+3)
    int pr = tid >> 6, pc = (tid & 63) * 4;
    const float* xpp = g_xp + ((size_t)(b0 + pr) * T_) * G_ + pc;

    // zero h buffers (256 floats total) + preload xbuf[0]
    ((float*)h1s)[tid] = 0.0f;                  // covers h1s+h2s (contiguous? no) —
    // be explicit:
    if (tid < 128) {
        h1s[tid >> 6][tid & 63] = 0.0f;
        h2s[tid >> 6][tid & 63] = 0.0f;
        *(float4*)&xbuf[0][pr][pc] = *(const float4*)xpp;
    }
    __syncthreads();

    for (int t = 0; t < T_; t++) {
        // ensure xp copy for step t (issued at t-1) has landed
        if (tid < 128 && t > 0) cp_wait0();

        // ---- P1: layer-1 recurrent gate partial dots ----
        u64 a[8];   // [g*2 + row]
#pragma unroll
        for (int i = 0; i < 8; i++) a[i] = 0ull;
        {
            const ulonglong2* hA = (const ulonglong2*)&h1s[0][s * 16];
            const ulonglong2* hB = (const ulonglong2*)&h1s[1][s * 16];
#pragma unroll
            for (int j = 0; j < 4; j++) {
                ulonglong2 u0 = hA[j];
                ulonglong2 u1 = hB[j];
#pragma unroll
                for (int g = 0; g < 4; g++) {
                    ffma2(a[2 * g + 0], w1[g][2 * j], u0.x);
                    ffma2(a[2 * g + 0], w1[g][2 * j + 1], u0.y);
                    ffma2(a[2 * g + 1], w1[g][2 * j], u1.x);
                    ffma2(a[2 * g + 1], w1[g][2 * j + 1], u1.y);
                }
            }
        }
        float v[8];
#pragma unroll
        for (int i = 0; i < 8; i++) {
            float2 f = unpk(a[i]);
            v[i] = f.x + f.y;
            v[i] += __shfl_xor_sync(0xffffffffu, v[i], 1);
            v[i] += __shfl_xor_sync(0xffffffffu, v[i], 2);
        }
        if (s == 0) {
            *(float4*)&ga[0][g0] = make_float4(v[0], v[2], v[4], v[6]);
            *(float4*)&ga[1][g0] = make_float4(v[1], v[3], v[5], v[7]);
        }
        __syncthreads();                       // B1

        // ---- U1: layer-1 activations (+ xp from smem) ----
        if (tid < 128) {
            const float* xb = &xbuf[t & 1][ur][0];
            float iv = sigf(ga[ur][uu] + xb[uu]);
            float fv = sigf(ga[ur][64 + uu] + xb[64 + uu]);
            float gv = tanhf_(ga[ur][128 + uu] + xb[128 + uu]);
            float ov = sigf(ga[ur][192 + uu] + xb[192 + uu]);
            c1v = fv * c1v + iv * gv;
            h1s[ur][uu] = ov * tanhf_(c1v);
            // kick off async copy of next step's xp
            if (t + 1 < T_) {
                cp_async16(&xbuf[(t + 1) & 1][pr][pc],
                           xpp + (size_t)(t + 1) * G_);
                cp_commit();
            }
        }
        __syncthreads();                       // B2

        // ---- P2: layer-2 gate partial dots over concat [h1new; h2prev] ----
#pragma unroll
        for (int i = 0; i < 8; i++) a[i] = 0ull;
        {
            const ulonglong2* pA;
            const ulonglong2* pB;
            if (s < 2) {
                pA = (const ulonglong2*)&h1s[0][s * 32];
                pB = (const ulonglong2*)&h1s[1][s * 32];
            } else {
                pA = (const ulonglong2*)&h2s[0][(s - 2) * 32];
                pB = (const ulonglong2*)&h2s[1][(s - 2) * 32];
            }
#pragma unroll
            for (int j = 0; j < 8; j++) {
                ulonglong2 u0 = pA[j];
                ulonglong2 u1 = pB[j];
#pragma unroll
                for (int g = 0; g < 4; g++) {
                    ffma2(a[2 * g + 0], w2[g][2 * j], u0.x);
                    ffma2(a[2 * g + 0], w2[g][2 * j + 1], u0.y);
                    ffma2(a[2 * g + 1], w2[g][2 * j], u1.x);
                    ffma2(a[2 * g + 1], w2[g][2 * j + 1], u1.y);
                }
            }
        }
#pragma unroll
        for (int i = 0; i < 8; i++) {
            float2 f = unpk(a[i]);
            v[i] = f.x + f.y;
            v[i] += __shfl_xor_sync(0xffffffffu, v[i], 1);
            v[i] += __shfl_xor_sync(0xffffffffu, v[i], 2);
        }
        if (s == 0) {
            *(float4*)&gb[0][g0] = make_float4(v[0] + bias2v.x, v[2] + bias2v.y,
                                               v[4] + bias2v.z, v[6] + bias2v.w);
            *(float4*)&gb[1][g0] = make_float4(v[1] + bias2v.x, v[3] + bias2v.y,
                                               v[5] + bias2v.z, v[7] + bias2v.w);
        }
        __syncthreads();                       // B3

        // ---- U2: layer-2 activations + output-head partials ----
        if (tid < 128) {
            float iv = sigf(gb[ur][uu]);
            float fv = sigf(gb[ur][64 + uu]);
            float gv = tanhf_(gb[ur][128 + uu]);
            float ov = sigf(gb[ur][192 + uu]);
            c2v = fv * c2v + iv * gv;
            float h2v = ov * tanhf_(c2v);
            h2s[ur][uu] = h2v;
            float p = wo * h2v;
#pragma unroll
            for (int off = 16; off > 0; off >>= 1)
                p += __shfl_xor_sync(0xffffffffu, p, off);
            if ((tid & 31) == 0) red[tid >> 5] = p;
        }
        __syncthreads();                       // B4

        if (tid < 2) {
            float r = red[2 * tid] + red[2 * tid + 1] + bo;
            r = fminf(fmaxf(r, 0.0f), 1.0f);
            out[(size_t)(b0 + tid) * T_ + t] = r;
        }
    }
}

// ---------------- launch ----------------
extern "C" void kernel_launch(void* const* d_in, const int* in_sizes, int n_in,
                              void* d_out, int out_size) {
    const float* x    = (const float*)d_in[0];
    const float* Wih1 = (const float*)d_in[1];
    const float* Whh1 = (const float*)d_in[2];
    const float* bih1 = (const float*)d_in[3];
    const float* bhh1 = (const float*)d_in[4];
    const float* Wih2 = (const float*)d_in[5];
    const float* Whh2 = (const float*)d_in[6];
    const float* bih2 = (const float*)d_in[7];
    const float* bhh2 = (const float*)d_in[8];
    const float* Wout = (const float*)d_in[9];
    const float* bout = (const float*)d_in[10];
    float* out = (float*)d_out;

    xp_gemm<<<dim3((B_ * T_) / 64, G_ / 64), 256>>>(x, Wih1, bih1, bhh1);
    lstm_rec<<<128, 256>>>(Whh1, Wih2, Whh2, bih2, bhh2, Wout, bout, out);
    (void)in_sizes; (void)n_in; (void)out_size;
}

// round 6
// speedup vs baseline: 1.6678x; 1.6678x over previous
#include <cuda_runtime.h>
#include <cstdint>

#define B_   256
#define T_   2048
#define IN_  128
#define H_   64
#define G_   256   // 4*H

// Scratch (allocation-free rule: static __device__ arrays)
__device__ float g_xp[(size_t)B_ * T_ * G_];   // precomputed x@W_ih1^T + b_ih1 + b_hh1
__device__ float g_Wt[IN_ * G_];               // W_ih1 transposed: [k][g]

typedef unsigned long long u64;

// ---------------- helpers ----------------
__device__ __forceinline__ void ffma2(u64& d, u64 a, u64 b) {
    asm("fma.rn.f32x2 %0, %1, %2, %0;" : "+l"(d) : "l"(a), "l"(b));
}
__device__ __forceinline__ float2 unpk(u64 p) {
    float2 r;
    asm("mov.b64 {%0, %1}, %2;" : "=f"(r.x), "=f"(r.y) : "l"(p));
    return r;
}
__device__ __forceinline__ u64 dup2(float a) {
    u64 r;
    asm("mov.b64 %0, {%1, %1};" : "=l"(r) : "f"(a));
    return r;
}
__device__ __forceinline__ float sigf(float x) {
    return __fdividef(1.0f, 1.0f + __expf(-x));
}
__device__ __forceinline__ float tanhf_(float x) {
    float a = fabsf(x);
    float e = __expf(2.0f * a);                 // inf-safe
    float r = 1.0f - __fdividef(2.0f, e + 1.0f);
    return copysignf(r, x);
}

// ---------------- kernel 1: transpose W_ih1 into k-major ----------------
__global__ void wt_kernel(const float* __restrict__ W) {
    int i = blockIdx.x * 256 + threadIdx.x;    // 32768 elems
    int n = i >> 7;
    int k = i & 127;
    g_Wt[k * G_ + n] = W[n * IN_ + k];
}

// ---------------- kernel 2: xp = x @ W_ih1^T + b_ih1 + b_hh1 ----------------
// (R2's proven version: W streamed k-major from g_Wt, L1-resident per n-tile)
__global__ __launch_bounds__(256) void xp_gemm(const float* __restrict__ x,
                                               const float* __restrict__ bih,
                                               const float* __restrict__ bhh) {
    __shared__ float Xs[64][128];              // 32 KB
    int tid = threadIdx.x;
    size_t mbase = (size_t)blockIdx.x * 64;
    int nbase = blockIdx.y * 64;

    const float* xg = x + mbase * IN_;
#pragma unroll
    for (int i = 0; i < 8; i++) {
        int idx = tid + i * 256;
        int m = idx >> 5, k4 = (idx & 31) << 2;
        *(float4*)&Xs[m][k4] = *(const float4*)(xg + m * IN_ + k4);
    }
    __syncthreads();

    int tx = tid & 15, ty = tid >> 4;
    int n0 = nbase + tx * 4;
    int m0 = ty * 4;

    u64 acc[4][2];
#pragma unroll
    for (int i = 0; i < 4; i++) { acc[i][0] = 0ull; acc[i][1] = 0ull; }

    const float* wt = g_Wt + n0;
#pragma unroll 8
    for (int k = 0; k < IN_; k++) {
        ulonglong2 bb = *(const ulonglong2*)(wt + k * G_);
#pragma unroll
        for (int i = 0; i < 4; i++) {
            u64 ap = dup2(Xs[m0 + i][k]);
            ffma2(acc[i][0], ap, bb.x);
            ffma2(acc[i][1], ap, bb.y);
        }
    }

    float4 bs;
    bs.x = bih[n0 + 0] + bhh[n0 + 0];
    bs.y = bih[n0 + 1] + bhh[n0 + 1];
    bs.z = bih[n0 + 2] + bhh[n0 + 2];
    bs.w = bih[n0 + 3] + bhh[n0 + 3];
#pragma unroll
    for (int i = 0; i < 4; i++) {
        float2 p0 = unpk(acc[i][0]);
        float2 p1 = unpk(acc[i][1]);
        float4 o = make_float4(p0.x + bs.x, p0.y + bs.y, p1.x + bs.z, p1.y + bs.w);
        *(float4*)(g_xp + (mbase + m0 + i) * G_ + n0) = o;
    }
}

// ---------------- kernel 3: fused 2-layer LSTM recurrence + output head ----------------
// 128 CTAs x 256 threads, 2 batch rows per CTA.
// Thread tid: q = tid>>2 (UNIT 0..63), s = tid&3 (K split).
// Thread owns ALL FOUR gates of unit q: rows {q, 64+q, 128+q, 192+q} of each W.
//   Layer-1 dot: k in [16s,16s+16) over h1;  Layer-2: kcat in [32s,32s+32).
// After the 2-level shfl allreduce over s, every lane holds the full gate sums
// for unit q (both batch rows) -> cell update happens LOCALLY (no gate smem,
// no activation phase). Lane s&1 selects which batch row it updates (c carried
// per lane); s==0/1 store h1/h2 for rows 0/1. xp and layer-2 bias are folded
// into the partial sums PRE-reduction (each lane adds its gate-s term once).
// Only 2 barriers per step.
__global__ __launch_bounds__(256, 1) void lstm_rec(
    const float* __restrict__ Whh1, const float* __restrict__ Wih2,
    const float* __restrict__ Whh2, const float* __restrict__ bih2,
    const float* __restrict__ bhh2, const float* __restrict__ Wout,
    const float* __restrict__ bout, float* __restrict__ out) {
    __shared__ float h1s[2][2][64];   // [parity][row][unit]
    __shared__ float h2s[2][2][64];
    __shared__ float red[16];         // [warp][row]

    int tid = threadIdx.x;
    int q = tid >> 2, s = tid & 3;
    int myrow = s & 1;

    // ---- weights into registers (gate-interleaved rows) ----
    u64 w1[4][8];    // [gate][k-pair]  k in [16s,16s+16)
    u64 w2[4][16];   // [gate][kc-pair] kcat in [32s,32s+32)
#pragma unroll
    for (int g = 0; g < 4; g++) {
        const u64* p1 = (const u64*)(Whh1 + (size_t)(g * 64 + q) * 64 + s * 16);
#pragma unroll
        for (int j = 0; j < 8; j++) w1[g][j] = p1[j];
        const float* b2 = (s < 2) ? (Wih2 + (size_t)(g * 64 + q) * 64 + s * 32)
                                  : (Whh2 + (size_t)(g * 64 + q) * 64 + (s - 2) * 32);
        const u64* p2 = (const u64*)b2;
#pragma unroll
        for (int j = 0; j < 16; j++) w2[g][j] = p2[j];
    }
    float b2v = bih2[s * 64 + q] + bhh2[s * 64 + q];   // bias of gate s*64+q
    float wo = Wout[q];
    float bo = bout[0];
    float c1 = 0.0f, c2 = 0.0f;                        // carries for row = myrow

    int b0 = blockIdx.x * 2;
    const float* xp0 = g_xp + (size_t)b0 * T_ * G_ + s * 64 + q;   // gate s*64+q
    const float* xp1 = xp0 + (size_t)T_ * G_;
    float xq0 = xp0[0];
    float xq1 = xp1[0];

    if (tid < 128) {                  // zero parity-1 (prv at t=0)
        h1s[1][tid >> 6][tid & 63] = 0.0f;
        h2s[1][tid >> 6][tid & 63] = 0.0f;
    }
    __syncthreads();

    for (int t = 0; t < T_; t++) {
        int cur = t & 1, prv = cur ^ 1;

        // ---- P1: layer-1 recurrent gate partial dots ----
        u64 a[8];   // [2*gate + row]
#pragma unroll
        for (int i = 0; i < 8; i++) a[i] = 0ull;
        {
            const ulonglong2* hA = (const ulonglong2*)&h1s[prv][0][s * 16];
            const ulonglong2* hB = (const ulonglong2*)&h1s[prv][1][s * 16];
#pragma unroll
            for (int j = 0; j < 4; j++) {
                ulonglong2 u0 = hA[j];
                ulonglong2 u1 = hB[j];
#pragma unroll
                for (int g = 0; g < 4; g++) {
                    ffma2(a[2 * g + 0], w1[g][2 * j], u0.x);
                    ffma2(a[2 * g + 0], w1[g][2 * j + 1], u0.y);
                    ffma2(a[2 * g + 1], w1[g][2 * j], u1.x);
                    ffma2(a[2 * g + 1], w1[g][2 * j + 1], u1.y);
                }
            }
        }
        float v[8];
#pragma unroll
        for (int i = 0; i < 8; i++) { float2 f = unpk(a[i]); v[i] = f.x + f.y; }
        // fold xp in once (lane s owns gate s); allreduce distributes it
#pragma unroll
        for (int g = 0; g < 4; g++) {
            v[2 * g + 0] += (s == g) ? xq0 : 0.0f;
            v[2 * g + 1] += (s == g) ? xq1 : 0.0f;
        }
#pragma unroll
        for (int i = 0; i < 8; i++) {
            v[i] += __shfl_xor_sync(0xffffffffu, v[i], 1);
            v[i] += __shfl_xor_sync(0xffffffffu, v[i], 2);
        }
        if (t + 1 < T_) {             // prefetch next step's xp (2 regs only)
            xq0 = xp0[(size_t)(t + 1) * G_];
            xq1 = xp1[(size_t)(t + 1) * G_];
        }

        // ---- cell-1 update (lane handles row=myrow; s and s+2 redundant) ----
        {
            float gi = myrow ? v[1] : v[0];
            float gf = myrow ? v[3] : v[2];
            float gg = myrow ? v[5] : v[4];
            float go = myrow ? v[7] : v[6];
            float iv = sigf(gi), fv = sigf(gf), gv = tanhf_(gg), ov = sigf(go);
            c1 = fv * c1 + iv * gv;
            float h1v = ov * tanhf_(c1);
            if (s < 2) h1s[cur][s][q] = h1v;
        }
        __syncthreads();              // B1: h1(cur) visible

        // ---- P2: layer-2 gates over concat [h1new(64); h2prev(64)] ----
#pragma unroll
        for (int i = 0; i < 8; i++) a[i] = 0ull;
        {
            const ulonglong2* pA;
            const ulonglong2* pB;
            if (s < 2) {
                pA = (const ulonglong2*)&h1s[cur][0][s * 32];
                pB = (const ulonglong2*)&h1s[cur][1][s * 32];
            } else {
                pA = (const ulonglong2*)&h2s[prv][0][(s - 2) * 32];
                pB = (const ulonglong2*)&h2s[prv][1][(s - 2) * 32];
            }
#pragma unroll
            for (int j = 0; j < 8; j++) {
                ulonglong2 u0 = pA[j];
                ulonglong2 u1 = pB[j];
#pragma unroll
                for (int g = 0; g < 4; g++) {
                    ffma2(a[2 * g + 0], w2[g][2 * j], u0.x);
                    ffma2(a[2 * g + 0], w2[g][2 * j + 1], u0.y);
                    ffma2(a[2 * g + 1], w2[g][2 * j], u1.x);
                    ffma2(a[2 * g + 1], w2[g][2 * j + 1], u1.y);
                }
            }
        }
#pragma unroll
        for (int i = 0; i < 8; i++) { float2 f = unpk(a[i]); v[i] = f.x + f.y; }
#pragma unroll
        for (int g = 0; g < 4; g++) {
            float bb = (s == g) ? b2v : 0.0f;
            v[2 * g + 0] += bb;
            v[2 * g + 1] += bb;
        }
#pragma unroll
        for (int i = 0; i < 8; i++) {
            v[i] += __shfl_xor_sync(0xffffffffu, v[i], 1);
            v[i] += __shfl_xor_sync(0xffffffffu, v[i], 2);
        }

        // ---- cell-2 update + output head ----
        {
            float gi = myrow ? v[1] : v[0];
            float gf = myrow ? v[3] : v[2];
            float gg = myrow ? v[5] : v[4];
            float go = myrow ? v[7] : v[6];
            float iv = sigf(gi), fv = sigf(gf), gv = tanhf_(gg), ov = sigf(go);
            c2 = fv * c2 + iv * gv;
            float h2v = ov * tanhf_(c2);
            if (s < 2) h2s[cur][s][q] = h2v;
            // head partial: reduce over the 8 units in this warp (lane bits 2-4)
            float p = wo * h2v;
            p += __shfl_xor_sync(0xffffffffu, p, 4);
            p += __shfl_xor_sync(0xffffffffu, p, 8);
            p += __shfl_xor_sync(0xffffffffu, p, 16);
            if ((tid & 31) < 2) red[(tid >> 5) * 2 + s] = p;
        }
        __syncthreads();              // B2: h2(cur) + red visible

        if (tid < 2) {
            float r = bo;
#pragma unroll
            for (int w = 0; w < 8; w++) r += red[w * 2 + tid];
            r = fminf(fmaxf(r, 0.0f), 1.0f);
            out[(size_t)(b0 + tid) * T_ + t] = r;
        }
    }
}

// ---------------- launch ----------------
extern "C" void kernel_launch(void* const* d_in, const int* in_sizes, int n_in,
                              void* d_out, int out_size) {
    const float* x    = (const float*)d_in[0];
    const float* Wih1 = (const float*)d_in[1];
    const float* Whh1 = (const float*)d_in[2];
    const float* bih1 = (const float*)d_in[3];
    const float* bhh1 = (const float*)d_in[4];
    const float* Wih2 = (const float*)d_in[5];
    const float* Whh2 = (const float*)d_in[6];
    const float* bih2 = (const float*)d_in[7];
    const float* bhh2 = (const float*)d_in[8];
    const float* Wout = (const float*)d_in[9];
    const float* bout = (const float*)d_in[10];
    float* out = (float*)d_out;

    wt_kernel<<<128, 256>>>(Wih1);
    xp_gemm<<<dim3((B_ * T_) / 64, G_ / 64), 256>>>(x, bih1, bhh1);
    lstm_rec<<<128, 256>>>(Whh1, Wih2, Whh2, bih2, bhh2, Wout, bout, out);
    (void)in_sizes; (void)n_in; (void)out_size;
}